// round 1
// baseline (speedup 1.0000x reference)
#include <cuda_runtime.h>
#include <cstdint>

#define TT   1024
#define BB   512
#define HD   64
#define GG   192   // 3*HD
#define NB   4     // batches per CTA
#define NCTA (BB / NB)

typedef unsigned long long ull;

// Layer-0 output scratch: (t, b, h) layout. __device__ global (no allocation).
__device__ float g_h1[(size_t)TT * BB * HD];

// ---------------- helpers ----------------

__device__ __forceinline__ ull fma2(ull a, ull b, ull c) {
    ull d;
    asm("fma.rn.f32x2 %0, %1, %2, %3;" : "=l"(d) : "l"(a), "l"(b), "l"(c));
    return d;
}

__device__ __forceinline__ ull pack2(float a, float b) {
    ull r;
    asm("mov.b64 %0, {%1, %2};" : "=l"(r) : "f"(a), "f"(b));
    return r;
}

__device__ __forceinline__ float sum2(ull v) {
    float x, y;
    asm("mov.b64 {%0, %1}, %2;" : "=f"(x), "=f"(y) : "l"(v));
    return x + y;
}

__device__ __forceinline__ float sigf(float x) {
    // 1 / (1 + 2^(-x*log2(e)))
    float e;
    asm("ex2.approx.f32 %0, %1;" : "=f"(e) : "f"(-1.4426950408889634f * x));
    float r;
    asm("rcp.approx.f32 %0, %1;" : "=f"(r) : "f"(1.0f + e));
    return r;
}

__device__ __forceinline__ float tanh_fast(float x) {
    float y;
    asm("tanh.approx.f32 %0, %1;" : "=f"(y) : "f"(x));
    return y;
}

// ---------------- layer 0 ----------------
// x: (B, T, 3). Writes g_h1 (t, b, h).
__global__ void __launch_bounds__(192, 1) gru_l0(
    const float* __restrict__ x,
    const float* __restrict__ Wih, const float* __restrict__ Whh,
    const float* __restrict__ bih, const float* __restrict__ bhh)
{
    __shared__ __align__(16) float hs[NB * HD];
    __shared__ float as_[NB * GG];
    __shared__ float bs_[NB * GG];
    __shared__ float xr[4][NB][3];

    const int tid = threadIdx.x;          // 0..191 = gate row
    const int b0  = blockIdx.x * NB;

    // W_hh row in registers as 32 packed f32x2 (row is 256B-aligned)
    ull w[32];
    const ull* wrow = (const ull*)(Whh + tid * HD);
#pragma unroll
    for (int i = 0; i < 32; i++) w[i] = wrow[i];

    const float bi  = bih[tid];
    const float bh  = bhh[tid];
    const float wi0 = Wih[tid * 3 + 0];
    const float wi1 = Wih[tid * 3 + 1];
    const float wi2 = Wih[tid * 3 + 2];

    for (int i = tid; i < NB * HD; i += 192) hs[i] = 0.0f;

    // prefetch x for t = 0, 1
    if (tid < 2 * NB * 3) {
        int t = tid / (NB * 3);
        int r = tid % (NB * 3);
        int b = r / 3, f = r % 3;
        xr[t][b][f] = x[(size_t)(b0 + b) * TT * 3 + t * 3 + f];
    }

    float hprev[NB];
#pragma unroll
    for (int b = 0; b < NB; b++) hprev[b] = 0.0f;

    __syncthreads();

    for (int t = 0; t < TT; t++) {
        const int sl = t & 3;
        // ---- phase 1: gx (3-wide) and gh (64-wide dot) per batch ----
#pragma unroll
        for (int b = 0; b < NB; b++) {
            float g = fmaf(wi2, xr[sl][b][2],
                      fmaf(wi1, xr[sl][b][1],
                      fmaf(wi0, xr[sl][b][0], bi)));
            as_[b * GG + tid] = g;
        }

        ull acc0[NB], acc1[NB];
#pragma unroll
        for (int b = 0; b < NB; b++) { acc0[b] = pack2(bh, 0.0f); acc1[b] = 0ull; }
#pragma unroll
        for (int k = 0; k < 16; k++) {
#pragma unroll
            for (int b = 0; b < NB; b++) {
                ulonglong2 hp = ((const ulonglong2*)(hs + b * HD))[k];
                acc0[b] = fma2(hp.x, w[2 * k],     acc0[b]);
                acc1[b] = fma2(hp.y, w[2 * k + 1], acc1[b]);
            }
        }
#pragma unroll
        for (int b = 0; b < NB; b++)
            bs_[b * GG + tid] = sum2(acc0[b]) + sum2(acc1[b]);

        __syncthreads();

        // ---- phase 2: gates (threads 0..63) + x prefetch (threads 128..139) ----
        if (tid < HD) {
#pragma unroll
            for (int b = 0; b < NB; b++) {
                float xrg = as_[b * GG + tid];
                float xzg = as_[b * GG + 64 + tid];
                float xng = as_[b * GG + 128 + tid];
                float hrg = bs_[b * GG + tid];
                float hzg = bs_[b * GG + 64 + tid];
                float hng = bs_[b * GG + 128 + tid];
                float r = sigf(xrg + hrg);
                float z = sigf(xzg + hzg);
                float n = tanh_fast(fmaf(r, hng, xng));
                float h = fmaf(z, hprev[b] - n, n);   // (1-z)*n + z*h
                hprev[b] = h;
                hs[b * HD + tid] = h;
                g_h1[((size_t)t * BB + b0 + b) * HD + tid] = h;
            }
        } else if (tid >= 128 && tid < 128 + NB * 3) {
            if (t + 2 < TT) {
                int r = tid - 128;
                int b = r / 3, f = r % 3;
                xr[(t + 2) & 3][b][f] =
                    x[(size_t)(b0 + b) * TT * 3 + (t + 2) * 3 + f];
            }
        }
        __syncthreads();
    }
}

// ---------------- layer 1 ----------------
// Reads g_h1 (t, b, h); writes seq_out (B, T, H) and final_hidden (B, H).
__global__ void __launch_bounds__(192, 1) gru_l1(
    const float* __restrict__ Wih, const float* __restrict__ Whh,
    const float* __restrict__ bih, const float* __restrict__ bhh,
    float* __restrict__ seq_out, float* __restrict__ fin)
{
    __shared__ __align__(16) float hs[NB * HD];
    __shared__ float as_[NB * GG];
    __shared__ float bs_[NB * GG];
    __shared__ __align__(16) float rs[4][NB][HD];

    const int tid = threadIdx.x;
    const int b0  = blockIdx.x * NB;

    ull w[32], wi[32];
    const ull* wrow  = (const ull*)(Whh + tid * HD);
    const ull* wirow = (const ull*)(Wih + tid * HD);
#pragma unroll
    for (int i = 0; i < 32; i++) { w[i] = wrow[i]; wi[i] = wirow[i]; }

    const float bi = bih[tid];
    const float bh = bhh[tid];

    for (int i = tid; i < NB * HD; i += 192) hs[i] = 0.0f;

    // prefetch h1 for t = 0, 1  (2 * NB * 16 = 128 float4 loads)
    if (tid < 128) {
        int t = tid / 64;
        int r = tid % 64;
        int b = r / 16, v = r % 16;
        ((float4*)rs[t][b])[v] =
            ((const float4*)(g_h1 + ((size_t)t * BB + b0 + b) * HD))[v];
    }

    float hprev[NB];
#pragma unroll
    for (int b = 0; b < NB; b++) hprev[b] = 0.0f;

    __syncthreads();

    for (int t = 0; t < TT; t++) {
        const int sl = t & 3;

        // ---- gx: dot(W_ih row, h1[t,b,:]) ----
        {
            ull a0[NB], a1[NB];
#pragma unroll
            for (int b = 0; b < NB; b++) { a0[b] = pack2(bi, 0.0f); a1[b] = 0ull; }
#pragma unroll
            for (int k = 0; k < 16; k++) {
#pragma unroll
                for (int b = 0; b < NB; b++) {
                    ulonglong2 hp = ((const ulonglong2*)rs[sl][b])[k];
                    a0[b] = fma2(hp.x, wi[2 * k],     a0[b]);
                    a1[b] = fma2(hp.y, wi[2 * k + 1], a1[b]);
                }
            }
#pragma unroll
            for (int b = 0; b < NB; b++)
                as_[b * GG + tid] = sum2(a0[b]) + sum2(a1[b]);
        }

        // ---- gh: dot(W_hh row, h[b,:]) ----
        {
            ull a0[NB], a1[NB];
#pragma unroll
            for (int b = 0; b < NB; b++) { a0[b] = pack2(bh, 0.0f); a1[b] = 0ull; }
#pragma unroll
            for (int k = 0; k < 16; k++) {
#pragma unroll
                for (int b = 0; b < NB; b++) {
                    ulonglong2 hp = ((const ulonglong2*)(hs + b * HD))[k];
                    a0[b] = fma2(hp.x, w[2 * k],     a0[b]);
                    a1[b] = fma2(hp.y, w[2 * k + 1], a1[b]);
                }
            }
#pragma unroll
            for (int b = 0; b < NB; b++)
                bs_[b * GG + tid] = sum2(a0[b]) + sum2(a1[b]);
        }

        __syncthreads();

        // ---- phase 2: gates (threads 0..63) + h1 prefetch (threads 128..191) ----
        if (tid < HD) {
#pragma unroll
            for (int b = 0; b < NB; b++) {
                float xrg = as_[b * GG + tid];
                float xzg = as_[b * GG + 64 + tid];
                float xng = as_[b * GG + 128 + tid];
                float hrg = bs_[b * GG + tid];
                float hzg = bs_[b * GG + 64 + tid];
                float hng = bs_[b * GG + 128 + tid];
                float r = sigf(xrg + hrg);
                float z = sigf(xzg + hzg);
                float n = tanh_fast(fmaf(r, hng, xng));
                float h = fmaf(z, hprev[b] - n, n);
                hprev[b] = h;
                hs[b * HD + tid] = h;
                seq_out[((size_t)(b0 + b) * TT + t) * HD + tid] = h;
                if (t == TT - 1) fin[(b0 + b) * HD + tid] = h;
            }
        } else if (tid >= 128) {
            if (t + 2 < TT) {
                int r = tid - 128;           // 0..63 = NB*16 float4 loads
                int b = r / 16, v = r % 16;
                ((float4*)rs[(t + 2) & 3][b])[v] =
                    ((const float4*)(g_h1 + ((size_t)(t + 2) * BB + b0 + b) * HD))[v];
            }
        }
        __syncthreads();
    }
}

// ---------------- launch ----------------

extern "C" void kernel_launch(void* const* d_in, const int* in_sizes, int n_in,
                              void* d_out, int out_size)
{
    const float* x     = (const float*)d_in[0];
    const float* Wih0  = (const float*)d_in[1];
    const float* Whh0  = (const float*)d_in[2];
    const float* bih0  = (const float*)d_in[3];
    const float* bhh0  = (const float*)d_in[4];
    const float* Wih1  = (const float*)d_in[5];
    const float* Whh1  = (const float*)d_in[6];
    const float* bih1  = (const float*)d_in[7];
    const float* bhh1  = (const float*)d_in[8];

    float* seq_out = (float*)d_out;
    float* fin     = seq_out + (size_t)BB * TT * HD;

    gru_l0<<<NCTA, 192>>>(x, Wih0, Whh0, bih0, bhh0);
    gru_l1<<<NCTA, 192>>>(Wih1, Whh1, bih1, bhh1, seq_out, fin);
}